// round 9
// baseline (speedup 1.0000x reference)
#include <cuda_runtime.h>
#include <cstdint>

// Problem constants
#define BB    128
#define LL    9
#define KK    3
#define PP    1680
#define CIN   256
#define COUT  256
#define ZR    1152
#define ZC    768
#define KSPLIT 2

typedef unsigned long long u64;

// Scratch (device globals: allocation-free)
__device__ float  g_Z[KSPLIT * ZR * ZC];   // 6.8 MB, 2 K-partials
__device__ float4 g_T[BB * 81 * 64];       // 10.6 MB  T[b][cc=g*27+c][o4]
__device__ int    g_codes[PP];

__device__ __forceinline__ u64 pack2(float lo, float hi) {
    u64 r;
    asm("mov.b64 %0, {%1, %2};" : "=l"(r) : "f"(lo), "f"(hi));
    return r;
}
__device__ __forceinline__ void unpack2(float& lo, float& hi, u64 v) {
    asm("mov.b64 {%0, %1}, %2;" : "=f"(lo), "=f"(hi) : "l"(v));
}
__device__ __forceinline__ void ffma2(u64& d, u64 a, u64 b) {
    asm("fma.rn.f32x2 %0, %1, %2, %3;" : "=l"(d) : "l"(a), "l"(b), "l"(d));
}

// ---------------------------------------------------------------------------
// Kernel 1: GEMM partial. Z[ks][r,j] = sum_{c in ks*128..+128} X[r,c]*Wm[j,c]
// 64x64 tile, two 64-wide K chunks, transposed smem, 4x4 reg tile via
// packed f32x2 FMAs, unroll-2 inner loop with distance-2 register prefetch.
// grid=(18,12,2)=432.  Blocks (bx<7, by==0, bz==0) also decode codes.
// ---------------------------------------------------------------------------
__global__ void __launch_bounds__(256) gemm_z(const float* __restrict__ X,
                                              const float* __restrict__ Wm,
                                              const float* __restrict__ M) {
    __shared__ float sXt[64][68];
    __shared__ float sWt[64][68];

    const int t  = threadIdx.x;
    const int rb = blockIdx.x * 64;
    const int jb = blockIdx.y * 64;
    const int kb = blockIdx.z * 128;

    // fused code decode (7 blocks x 256 threads >= 1680)
    if (blockIdx.y == 0 && blockIdx.z == 0 && blockIdx.x < 7) {
        int p = blockIdx.x * 256 + t;
        if (p < PP) {
            const int PL = PP * LL;
            int c[3] = {0, 0, 0};
            const int w3[3] = {1, 3, 9};
#pragma unroll
            for (int l = 0; l < LL; l++) {
                float m1 = M[PL + p * LL + l];
                float m2 = M[2 * PL + p * LL + l];
                int a = (m1 > 0.5f) ? 1 : ((m2 > 0.5f) ? 2 : 0);
                c[l / 3] += a * w3[l % 3];
            }
            g_codes[p] = c[0] | (c[1] << 8) | (c[2] << 16);
        }
    }

    const int c4 = t & 15;
    const int rr = t >> 4;

    // packed accumulators: ap0[j] = {acc[0][j], acc[1][j]},
    //                      ap1[j] = {acc[2][j], acc[3][j]}
    u64 ap0[4] = {0, 0, 0, 0};
    u64 ap1[4] = {0, 0, 0, 0};

    const int row0 = (t >> 4) * 4;
    const int col0 = (t & 15) * 4;

#pragma unroll
    for (int kk = 0; kk < 2; kk++) {
        const int kc = kb + kk * 64;
#pragma unroll
        for (int i = 0; i < 4; i++) {
            int r = rr + i * 16;
            float4 v = *(const float4*)&X[(rb + r) * CIN + kc + c4 * 4];
            sXt[c4 * 4 + 0][r] = v.x;
            sXt[c4 * 4 + 1][r] = v.y;
            sXt[c4 * 4 + 2][r] = v.z;
            sXt[c4 * 4 + 3][r] = v.w;
            float4 w = *(const float4*)&Wm[(jb + r) * CIN + kc + c4 * 4];
            sWt[c4 * 4 + 0][r] = w.x;
            sWt[c4 * 4 + 1][r] = w.y;
            sWt[c4 * 4 + 2][r] = w.z;
            sWt[c4 * 4 + 3][r] = w.w;
        }
        __syncthreads();

        // distance-2 rotating prefetch
        ulonglong2 xpA = *(const ulonglong2*)&sXt[0][row0];
        float4     wvA = *(const float4*)&sWt[0][col0];
        ulonglong2 xpB = *(const ulonglong2*)&sXt[1][row0];
        float4     wvB = *(const float4*)&sWt[1][col0];

#pragma unroll
        for (int c = 0; c < 64; c += 2) {
            // consume A (iter c), prefetch c+2 into A
            {
                ulonglong2 xc = xpA;
                float4 wc = wvA;
                if (c + 2 < 64) {
                    xpA = *(const ulonglong2*)&sXt[c + 2][row0];
                    wvA = *(const float4*)&sWt[c + 2][col0];
                }
                u64 w0 = pack2(wc.x, wc.x);
                u64 w1 = pack2(wc.y, wc.y);
                u64 w2 = pack2(wc.z, wc.z);
                u64 w3 = pack2(wc.w, wc.w);
                ffma2(ap0[0], xc.x, w0);
                ffma2(ap0[1], xc.x, w1);
                ffma2(ap0[2], xc.x, w2);
                ffma2(ap0[3], xc.x, w3);
                ffma2(ap1[0], xc.y, w0);
                ffma2(ap1[1], xc.y, w1);
                ffma2(ap1[2], xc.y, w2);
                ffma2(ap1[3], xc.y, w3);
            }
            // consume B (iter c+1), prefetch c+3 into B
            {
                ulonglong2 xc = xpB;
                float4 wc = wvB;
                if (c + 3 < 64) {
                    xpB = *(const ulonglong2*)&sXt[c + 3][row0];
                    wvB = *(const float4*)&sWt[c + 3][col0];
                }
                u64 w0 = pack2(wc.x, wc.x);
                u64 w1 = pack2(wc.y, wc.y);
                u64 w2 = pack2(wc.z, wc.z);
                u64 w3 = pack2(wc.w, wc.w);
                ffma2(ap0[0], xc.x, w0);
                ffma2(ap0[1], xc.x, w1);
                ffma2(ap0[2], xc.x, w2);
                ffma2(ap0[3], xc.x, w3);
                ffma2(ap1[0], xc.y, w0);
                ffma2(ap1[1], xc.y, w1);
                ffma2(ap1[2], xc.y, w2);
                ffma2(ap1[3], xc.y, w3);
            }
        }
        __syncthreads();
    }

    // unpack and store
    float acc[4][4];
#pragma unroll
    for (int j = 0; j < 4; j++) {
        unpack2(acc[0][j], acc[1][j], ap0[j]);
        unpack2(acc[2][j], acc[3][j], ap1[j]);
    }
    float4* Z4 = (float4*)(g_Z + blockIdx.z * (ZR * ZC));
#pragma unroll
    for (int i = 0; i < 4; i++) {
        float4 v = make_float4(acc[i][0], acc[i][1], acc[i][2], acc[i][3]);
        Z4[(rb + row0 + i) * (ZC / 4) + (jb + col0) / 4] = v;
    }
}

// ---------------------------------------------------------------------------
// Kernel 2: build T[b][cc][o4]. Sum the K-partials of this b's 27x64-f4
// Z slice into smem, then build the 81-entry table from smem.
// One block per b, 256 threads.
// ---------------------------------------------------------------------------
__global__ void __launch_bounds__(256) build_T() {
    __shared__ float4 sZ[27 * 64];

    const int t = threadIdx.x;
    const int b = blockIdx.x;

    const float4* Z0 = (const float4*)g_Z;
    const int pstride = (ZR * ZC) / 4;
    const int zb = b * LL * KK * (COUT / 4);

#pragma unroll 2
    for (int i = t; i < 27 * 64; i += 256) {
        int idx = zb + i;                 // i = vr*64 + o4, vr = l*3 + k
        float4 a = Z0[idx];
        float4 bb = Z0[idx + pstride];
        float4 s;
        s.x = a.x + bb.x;
        s.y = a.y + bb.y;
        s.z = a.z + bb.z;
        s.w = a.w + bb.w;
        sZ[i] = s;
    }
    __syncthreads();

    const int tb = b * 81 * 64;
#pragma unroll 2
    for (int i = t; i < 81 * 64; i += 256) {
        int o4 = i & 63;
        int cc = i >> 6;             // g*27 + c
        int g  = cc / 27;
        int c  = cc - g * 27;
        int d0 = c % 3, d1 = (c / 3) % 3, d2 = c / 9;
        // vr = 9g + 3j + d_j
        float4 v0 = sZ[(9 * g + 0 + d0) * 64 + o4];
        float4 v1 = sZ[(9 * g + 3 + d1) * 64 + o4];
        float4 v2 = sZ[(9 * g + 6 + d2) * 64 + o4];
        float4 s;
        s.x = v0.x + v1.x + v2.x;
        s.y = v0.y + v1.y + v2.y;
        s.z = v0.z + v1.z + v2.z;
        s.w = v0.w + v1.w + v2.w;
        g_T[tb + i] = s;
    }
}

// ---------------------------------------------------------------------------
// Kernel 3: combine. Copy the 81x32-f4 table slice from L2-resident g_T into
// smem, then each output float4 = T0[c0]+T1[c1]+T2[c2], streamed to GMEM.
// grid = (5 p-chunks of 336, 2 channel halves, 128 b), 256 threads.
// ---------------------------------------------------------------------------
#define PCHUNK 336
#define NCHUNK 5

__global__ void __launch_bounds__(256) perm_combine(float* __restrict__ out) {
    __shared__ float4 sT4[81 * 32];
    __shared__ int sCodes[PCHUNK];

    const int t     = threadIdx.x;
    const int chunk = blockIdx.x;
    const int h     = blockIdx.y;
    const int b     = blockIdx.z;
    const int pbase = chunk * PCHUNK;

    const int tb = b * 81 * 64 + h * 32;
#pragma unroll 2
    for (int i = t; i < 81 * 32; i += 256) {
        int cc = i >> 5;
        int o4 = i & 31;
        sT4[i] = g_T[tb + cc * 64 + o4];
    }
    for (int i = t; i < PCHUNK; i += 256) sCodes[i] = g_codes[pbase + i];
    __syncthreads();

    const int o4 = t & 31;
    const int pw = t >> 5;
    float4* out4 = (float4*)out;
    const int obase = (b * PP + pbase) * (COUT / 4) + h * 32 + o4;

#pragma unroll 2
    for (int it = 0; it < PCHUNK / 8; it++) {
        int po   = it * 8 + pw;
        int code = sCodes[po];
        int c0 = code & 0xFF;
        int c1 = (code >> 8) & 0xFF;
        int c2 = (code >> 16) & 0xFF;
        float4 a  = sT4[c0 * 32 + o4];
        float4 bb = sT4[(27 + c1) * 32 + o4];
        float4 cv = sT4[(54 + c2) * 32 + o4];
        float4 r;
        r.x = a.x + bb.x + cv.x;
        r.y = a.y + bb.y + cv.y;
        r.z = a.z + bb.z + cv.z;
        r.w = a.w + bb.w + cv.w;
        __stcs(&out4[obase + po * (COUT / 4)], r);
    }
}

// ---------------------------------------------------------------------------
extern "C" void kernel_launch(void* const* d_in, const int* in_sizes, int n_in,
                              void* d_out, int out_size) {
    (void)in_sizes; (void)n_in; (void)out_size;
    const float* x = (const float*)d_in[0];  // (128, 9, 256)
    const float* W = (const float*)d_in[1];  // (3, 256, 256)
    const float* M = (const float*)d_in[2];  // (3, 1680, 9)
    float* out = (float*)d_out;              // (128, 1680, 256)

    gemm_z<<<dim3(18, 12, KSPLIT), 256>>>(x, W, M);
    build_T<<<BB, 256>>>();
    perm_combine<<<dim3(NCHUNK, 2, BB), 256>>>(out);
}

// round 11
// speedup vs baseline: 1.0753x; 1.0753x over previous
#include <cuda_runtime.h>
#include <cstdint>

// Problem constants
#define BB    128
#define LL    9
#define KK    3
#define PP    1680
#define CIN   256
#define COUT  256
#define ZR    1152
#define ZC    768
#define KSPLIT 2

typedef unsigned long long u64;

// Scratch (device globals: allocation-free)
__device__ float  g_Z[KSPLIT * ZR * ZC];   // 6.8 MB, 2 K-partials
__device__ float4 g_T[BB * 81 * 64];       // 10.6 MB  T[b][cc=g*27+c][o4]
__device__ int    g_codes[PP];

__device__ __forceinline__ u64 pack2(float lo, float hi) {
    u64 r;
    asm("mov.b64 %0, {%1, %2};" : "=l"(r) : "f"(lo), "f"(hi));
    return r;
}
__device__ __forceinline__ void unpack2(float& lo, float& hi, u64 v) {
    asm("mov.b64 {%0, %1}, %2;" : "=f"(lo), "=f"(hi) : "l"(v));
}
__device__ __forceinline__ void ffma2(u64& d, u64 a, u64 b) {
    asm("fma.rn.f32x2 %0, %1, %2, %3;" : "=l"(d) : "l"(a), "l"(b), "l"(d));
}

// Swizzled transposed tile: logical [c][r] (c = k-index row, r = output idx)
// physical float offset = c*64 + 4*((r>>2) ^ ((c>>2)&15)) + (r&3)
// -> stores 2-way max, vector reads conflict-free, 16B alignment preserved.

// ---------------------------------------------------------------------------
// Kernel 1: GEMM partial. Z[ks][r,j] = sum_{c in ks*128..+128} X[r,c]*Wm[j,c]
// 64x64 tile, two 64-wide K chunks, XOR-swizzled transposed smem tiles,
// 4x4 reg tile via packed f32x2 FMAs, register prefetch. grid=(18,12,2).
// Blocks (bx<7, by==0, bz==0) also decode permutation codes from M.
// ---------------------------------------------------------------------------
__global__ void __launch_bounds__(256) gemm_z(const float* __restrict__ X,
                                              const float* __restrict__ Wm,
                                              const float* __restrict__ M) {
    __shared__ float sX[64 * 64];
    __shared__ float sW[64 * 64];

    const int t  = threadIdx.x;
    const int rb = blockIdx.x * 64;
    const int jb = blockIdx.y * 64;
    const int kb = blockIdx.z * 128;

    // fused code decode (7 blocks x 256 threads >= 1680)
    if (blockIdx.y == 0 && blockIdx.z == 0 && blockIdx.x < 7) {
        int p = blockIdx.x * 256 + t;
        if (p < PP) {
            const int PL = PP * LL;
            int c[3] = {0, 0, 0};
            const int w3[3] = {1, 3, 9};
#pragma unroll
            for (int l = 0; l < LL; l++) {
                float m1 = M[PL + p * LL + l];
                float m2 = M[2 * PL + p * LL + l];
                int a = (m1 > 0.5f) ? 1 : ((m2 > 0.5f) ? 2 : 0);
                c[l / 3] += a * w3[l % 3];
            }
            g_codes[p] = c[0] | (c[1] << 8) | (c[2] << 16);
        }
    }

    const int c4 = t & 15;   // float4 index along c during loads; also (c>>2) key
    const int rr = t >> 4;   // base output-index during loads

    const int gx = t >> 4;   // x read granule  (= row0>>2)
    const int gw = t & 15;   // w read granule  (= col0>>2)
    const int row0 = gx * 4;
    const int col0 = gw * 4;

    // packed accumulators: ap0[j] = {acc[0][j], acc[1][j]},
    //                      ap1[j] = {acc[2][j], acc[3][j]}
    u64 ap0[4] = {0, 0, 0, 0};
    u64 ap1[4] = {0, 0, 0, 0};

#pragma unroll
    for (int kk = 0; kk < 2; kk++) {
        const int kc = kb + kk * 64;
#pragma unroll
        for (int i = 0; i < 4; i++) {
            int r = rr + i * 16;
            // scatter float4 (along c) into 4 swizzled rows c4*4+j
            int gs = (((r >> 2) ^ c4) << 2) + (r & 3);
            float4 v = *(const float4*)&X[(rb + r) * CIN + kc + c4 * 4];
            float* px = &sX[c4 * 256 + gs];
            px[0]   = v.x;
            px[64]  = v.y;
            px[128] = v.z;
            px[192] = v.w;
            float4 w = *(const float4*)&Wm[(jb + r) * CIN + kc + c4 * 4];
            float* pw = &sW[c4 * 256 + gs];
            pw[0]   = w.x;
            pw[64]  = w.y;
            pw[128] = w.z;
            pw[192] = w.w;
        }
        __syncthreads();

        // register prefetch (distance 1)
        ulonglong2 xp = *(const ulonglong2*)&sX[(gx ^ 0) << 2];
        float4     wv = *(const float4*)&sW[(gw ^ 0) << 2];
#pragma unroll
        for (int c = 0; c < 64; c++) {
            ulonglong2 xc = xp;
            float4 wc = wv;
            if (c < 63) {
                int key = ((c + 1) >> 2) & 15;
                xp = *(const ulonglong2*)&sX[(c + 1) * 64 + ((gx ^ key) << 2)];
                wv = *(const float4*)&sW[(c + 1) * 64 + ((gw ^ key) << 2)];
            }
            u64 w0 = pack2(wc.x, wc.x);
            u64 w1 = pack2(wc.y, wc.y);
            u64 w2 = pack2(wc.z, wc.z);
            u64 w3 = pack2(wc.w, wc.w);
            ffma2(ap0[0], xc.x, w0);
            ffma2(ap0[1], xc.x, w1);
            ffma2(ap0[2], xc.x, w2);
            ffma2(ap0[3], xc.x, w3);
            ffma2(ap1[0], xc.y, w0);
            ffma2(ap1[1], xc.y, w1);
            ffma2(ap1[2], xc.y, w2);
            ffma2(ap1[3], xc.y, w3);
        }
        __syncthreads();
    }

    // unpack and store
    float acc[4][4];
#pragma unroll
    for (int j = 0; j < 4; j++) {
        unpack2(acc[0][j], acc[1][j], ap0[j]);
        unpack2(acc[2][j], acc[3][j], ap1[j]);
    }
    float4* Z4 = (float4*)(g_Z + blockIdx.z * (ZR * ZC));
#pragma unroll
    for (int i = 0; i < 4; i++) {
        float4 v = make_float4(acc[i][0], acc[i][1], acc[i][2], acc[i][3]);
        Z4[(rb + row0 + i) * (ZC / 4) + (jb + col0) / 4] = v;
    }
}

// ---------------------------------------------------------------------------
// Kernel 2: build T[b][cc][o4]. Sum the K-partials of this b's 27x64-f4
// Z slice into smem, then build the 81-entry table from smem.
// One block per b, 256 threads.
// ---------------------------------------------------------------------------
__global__ void __launch_bounds__(256) build_T() {
    __shared__ float4 sZ[27 * 64];

    const int t = threadIdx.x;
    const int b = blockIdx.x;

    const float4* Z0 = (const float4*)g_Z;
    const int pstride = (ZR * ZC) / 4;
    const int zb = b * LL * KK * (COUT / 4);

#pragma unroll 2
    for (int i = t; i < 27 * 64; i += 256) {
        int idx = zb + i;                 // i = vr*64 + o4, vr = l*3 + k
        float4 a = Z0[idx];
        float4 bb = Z0[idx + pstride];
        float4 s;
        s.x = a.x + bb.x;
        s.y = a.y + bb.y;
        s.z = a.z + bb.z;
        s.w = a.w + bb.w;
        sZ[i] = s;
    }
    __syncthreads();

    const int tb = b * 81 * 64;
#pragma unroll 2
    for (int i = t; i < 81 * 64; i += 256) {
        int o4 = i & 63;
        int cc = i >> 6;             // g*27 + c
        int g  = cc / 27;
        int c  = cc - g * 27;
        int d0 = c % 3, d1 = (c / 3) % 3, d2 = c / 9;
        // vr = 9g + 3j + d_j
        float4 v0 = sZ[(9 * g + 0 + d0) * 64 + o4];
        float4 v1 = sZ[(9 * g + 3 + d1) * 64 + o4];
        float4 v2 = sZ[(9 * g + 6 + d2) * 64 + o4];
        float4 s;
        s.x = v0.x + v1.x + v2.x;
        s.y = v0.y + v1.y + v2.y;
        s.z = v0.z + v1.z + v2.z;
        s.w = v0.w + v1.w + v2.w;
        g_T[tb + i] = s;
    }
}

// ---------------------------------------------------------------------------
// Kernel 3: combine. Copy the 81x32-f4 table slice from L2-resident g_T into
// smem, then each output float4 = T0[c0]+T1[c1]+T2[c2], streamed to GMEM.
// grid = (5 p-chunks of 336, 2 channel halves, 128 b), 256 threads.
// ---------------------------------------------------------------------------
#define PCHUNK 336
#define NCHUNK 5

__global__ void __launch_bounds__(256) perm_combine(float* __restrict__ out) {
    __shared__ float4 sT4[81 * 32];
    __shared__ int sCodes[PCHUNK];

    const int t     = threadIdx.x;
    const int chunk = blockIdx.x;
    const int h     = blockIdx.y;
    const int b     = blockIdx.z;
    const int pbase = chunk * PCHUNK;

    const int tb = b * 81 * 64 + h * 32;
#pragma unroll 2
    for (int i = t; i < 81 * 32; i += 256) {
        int cc = i >> 5;
        int o4 = i & 31;
        sT4[i] = g_T[tb + cc * 64 + o4];
    }
    for (int i = t; i < PCHUNK; i += 256) sCodes[i] = g_codes[pbase + i];
    __syncthreads();

    const int o4 = t & 31;
    const int pw = t >> 5;
    float4* out4 = (float4*)out;
    const int obase = (b * PP + pbase) * (COUT / 4) + h * 32 + o4;

#pragma unroll 2
    for (int it = 0; it < PCHUNK / 8; it++) {
        int po   = it * 8 + pw;
        int code = sCodes[po];
        int c0 = code & 0xFF;
        int c1 = (code >> 8) & 0xFF;
        int c2 = (code >> 16) & 0xFF;
        float4 a  = sT4[c0 * 32 + o4];
        float4 bb = sT4[(27 + c1) * 32 + o4];
        float4 cv = sT4[(54 + c2) * 32 + o4];
        float4 r;
        r.x = a.x + bb.x + cv.x;
        r.y = a.y + bb.y + cv.y;
        r.z = a.z + bb.z + cv.z;
        r.w = a.w + bb.w + cv.w;
        __stcs(&out4[obase + po * (COUT / 4)], r);
    }
}

// ---------------------------------------------------------------------------
extern "C" void kernel_launch(void* const* d_in, const int* in_sizes, int n_in,
                              void* d_out, int out_size) {
    (void)in_sizes; (void)n_in; (void)out_size;
    const float* x = (const float*)d_in[0];  // (128, 9, 256)
    const float* W = (const float*)d_in[1];  // (3, 256, 256)
    const float* M = (const float*)d_in[2];  // (3, 1680, 9)
    float* out = (float*)d_out;              // (128, 1680, 256)

    gemm_z<<<dim3(18, 12, KSPLIT), 256>>>(x, W, M);
    build_T<<<BB, 256>>>();
    perm_combine<<<dim3(NCHUNK, 2, BB), 256>>>(out);
}

// round 14
// speedup vs baseline: 1.1003x; 1.0233x over previous
#include <cuda_runtime.h>
#include <cstdint>

// Problem constants
#define BB    128
#define LL    9
#define KK    3
#define PP    1680
#define CIN   256
#define COUT  256
#define ZR    1152
#define ZC    768
#define KSPLIT 2

typedef unsigned long long u64;

// Scratch (device globals: allocation-free)
__device__ float  g_Z[KSPLIT * ZR * ZC];   // 6.8 MB, 2 K-partials
__device__ int    g_codes[PP];

__device__ __forceinline__ u64 pack2(float lo, float hi) {
    u64 r;
    asm("mov.b64 %0, {%1, %2};" : "=l"(r) : "f"(lo), "f"(hi));
    return r;
}
__device__ __forceinline__ void unpack2(float& lo, float& hi, u64 v) {
    asm("mov.b64 {%0, %1}, %2;" : "=f"(lo), "=f"(hi) : "l"(v));
}
__device__ __forceinline__ void ffma2(u64& d, u64 a, u64 b) {
    asm("fma.rn.f32x2 %0, %1, %2, %3;" : "=l"(d) : "l"(a), "l"(b), "l"(d));
}

// Swizzled transposed tile: logical [c][r]
// physical float offset = c*64 + 4*((r>>2) ^ ((c>>2)&15)) + (r&3)

// ---------------------------------------------------------------------------
// Kernel 1: GEMM partial. Z[ks][r,j] = sum_{c in ks*128..+128} X[r,c]*Wm[j,c]
// 64x64 tile, two 64-wide K chunks, XOR-swizzled transposed smem tiles,
// 4x4 reg tile via packed f32x2 FMAs, register prefetch. grid=(18,12,2).
// Blocks (bx<7, by==0, bz==0) also decode permutation codes from M.
// ---------------------------------------------------------------------------
__global__ void __launch_bounds__(256) gemm_z(const float* __restrict__ X,
                                              const float* __restrict__ Wm,
                                              const float* __restrict__ M) {
    __shared__ float sX[64 * 64];
    __shared__ float sW[64 * 64];

    const int t  = threadIdx.x;
    const int rb = blockIdx.x * 64;
    const int jb = blockIdx.y * 64;
    const int kb = blockIdx.z * 128;

    // fused code decode (7 blocks x 256 threads >= 1680)
    if (blockIdx.y == 0 && blockIdx.z == 0 && blockIdx.x < 7) {
        int p = blockIdx.x * 256 + t;
        if (p < PP) {
            const int PL = PP * LL;
            int c[3] = {0, 0, 0};
            const int w3[3] = {1, 3, 9};
#pragma unroll
            for (int l = 0; l < LL; l++) {
                float m1 = M[PL + p * LL + l];
                float m2 = M[2 * PL + p * LL + l];
                int a = (m1 > 0.5f) ? 1 : ((m2 > 0.5f) ? 2 : 0);
                c[l / 3] += a * w3[l % 3];
            }
            g_codes[p] = c[0] | (c[1] << 8) | (c[2] << 16);
        }
    }

    const int c4 = t & 15;
    const int rr = t >> 4;

    const int gx = t >> 4;
    const int gw = t & 15;
    const int row0 = gx * 4;
    const int col0 = gw * 4;

    u64 ap0[4] = {0, 0, 0, 0};
    u64 ap1[4] = {0, 0, 0, 0};

#pragma unroll
    for (int kk = 0; kk < 2; kk++) {
        const int kc = kb + kk * 64;
#pragma unroll
        for (int i = 0; i < 4; i++) {
            int r = rr + i * 16;
            int gs = (((r >> 2) ^ c4) << 2) + (r & 3);
            float4 v = *(const float4*)&X[(rb + r) * CIN + kc + c4 * 4];
            float* px = &sX[c4 * 256 + gs];
            px[0]   = v.x;
            px[64]  = v.y;
            px[128] = v.z;
            px[192] = v.w;
            float4 w = *(const float4*)&Wm[(jb + r) * CIN + kc + c4 * 4];
            float* pw = &sW[c4 * 256 + gs];
            pw[0]   = w.x;
            pw[64]  = w.y;
            pw[128] = w.z;
            pw[192] = w.w;
        }
        __syncthreads();

        ulonglong2 xp = *(const ulonglong2*)&sX[(gx ^ 0) << 2];
        float4     wv = *(const float4*)&sW[(gw ^ 0) << 2];
#pragma unroll
        for (int c = 0; c < 64; c++) {
            ulonglong2 xc = xp;
            float4 wc = wv;
            if (c < 63) {
                int key = ((c + 1) >> 2) & 15;
                xp = *(const ulonglong2*)&sX[(c + 1) * 64 + ((gx ^ key) << 2)];
                wv = *(const float4*)&sW[(c + 1) * 64 + ((gw ^ key) << 2)];
            }
            u64 w0 = pack2(wc.x, wc.x);
            u64 w1 = pack2(wc.y, wc.y);
            u64 w2 = pack2(wc.z, wc.z);
            u64 w3 = pack2(wc.w, wc.w);
            ffma2(ap0[0], xc.x, w0);
            ffma2(ap0[1], xc.x, w1);
            ffma2(ap0[2], xc.x, w2);
            ffma2(ap0[3], xc.x, w3);
            ffma2(ap1[0], xc.y, w0);
            ffma2(ap1[1], xc.y, w1);
            ffma2(ap1[2], xc.y, w2);
            ffma2(ap1[3], xc.y, w3);
        }
        __syncthreads();
    }

    float acc[4][4];
#pragma unroll
    for (int j = 0; j < 4; j++) {
        unpack2(acc[0][j], acc[1][j], ap0[j]);
        unpack2(acc[2][j], acc[3][j], ap1[j]);
    }
    float4* Z4 = (float4*)(g_Z + blockIdx.z * (ZR * ZC));
#pragma unroll
    for (int i = 0; i < 4; i++) {
        float4 v = make_float4(acc[i][0], acc[i][1], acc[i][2], acc[i][3]);
        Z4[(rb + row0 + i) * (ZC / 4) + (jb + col0) / 4] = v;
    }
}

// ---------------------------------------------------------------------------
// Kernel 2 (fused): combine. Stage this (b, half)'s summed Z slice
// (27 vrows x 32 f4, both K-partials) into smem, build the 81-entry
// partial-sum table in smem, then stream 840 permutations' outputs.
// grid = (2 p-chunks of 840, 2 channel halves, 128 b), 256 threads.
// smem = 13.5 + 41.5 + 3.3 KB = 58.3 KB -> 3 CTAs/SM.
// ---------------------------------------------------------------------------
#define PCHUNK 840
#define NCHUNK 2

__global__ void __launch_bounds__(256) perm_combine(float* __restrict__ out) {
    __shared__ float4 sT4[81 * 32];
    __shared__ float4 sZ[27 * 32];
    __shared__ int sCodes[PCHUNK];

    const int t     = threadIdx.x;
    const int chunk = blockIdx.x;
    const int h     = blockIdx.y;
    const int b     = blockIdx.z;
    const int pbase = chunk * PCHUNK;

    // ---- stage summed Z slice (both K-partials): vr = l*3 + k ----
    const float4* Z0 = (const float4*)g_Z;
    const int pstride = (ZR * ZC) / 4;
    const int zb = b * LL * (ZC / 4) + h * 32;
    for (int i = t; i < 27 * 32; i += 256) {
        int vr = i >> 5;
        int o4 = i & 31;
        int l = vr / 3, k = vr - 3 * l;
        int idx = zb + l * (ZC / 4) + k * (COUT / 4) + o4;
        float4 a = Z0[idx];
        float4 bb = Z0[idx + pstride];
        float4 s;
        s.x = a.x + bb.x;
        s.y = a.y + bb.y;
        s.z = a.z + bb.z;
        s.w = a.w + bb.w;
        sZ[i] = s;
    }
#pragma unroll 2
    for (int i = t; i < PCHUNK; i += 256) sCodes[i] = g_codes[pbase + i];
    __syncthreads();

    // ---- build 81-entry table from smem ----
    for (int i = t; i < 81 * 32; i += 256) {
        int cc = i >> 5;
        int o4 = i & 31;
        int g  = cc / 27;
        int c  = cc - g * 27;
        int d0 = c % 3, d1 = (c / 3) % 3, d2 = c / 9;
        // vr = 9g + 3j + d_j   (here vr within group g: 3*0+d0, 3*1+d1, 3*2+d2)
        float4 v0 = sZ[(9 * g + 0 + d0) * 32 + o4];
        float4 v1 = sZ[(9 * g + 3 + d1) * 32 + o4];
        float4 v2 = sZ[(9 * g + 6 + d2) * 32 + o4];
        float4 s;
        s.x = v0.x + v1.x + v2.x;
        s.y = v0.y + v1.y + v2.y;
        s.z = v0.z + v1.z + v2.z;
        s.w = v0.w + v1.w + v2.w;
        sT4[i] = s;
    }
    __syncthreads();

    // ---- combine + stream out ----
    const int o4 = t & 31;
    const int pw = t >> 5;
    float4* out4 = (float4*)out;
    const int obase = (b * PP + pbase) * (COUT / 4) + h * 32 + o4;

#pragma unroll 2
    for (int it = 0; it < PCHUNK / 8; it++) {
        int po   = it * 8 + pw;
        int code = sCodes[po];
        int c0 = code & 0xFF;
        int c1 = (code >> 8) & 0xFF;
        int c2 = (code >> 16) & 0xFF;
        float4 a  = sT4[c0 * 32 + o4];
        float4 bb = sT4[(27 + c1) * 32 + o4];
        float4 cv = sT4[(54 + c2) * 32 + o4];
        float4 r;
        r.x = a.x + bb.x + cv.x;
        r.y = a.y + bb.y + cv.y;
        r.z = a.z + bb.z + cv.z;
        r.w = a.w + bb.w + cv.w;
        __stcs(&out4[obase + po * (COUT / 4)], r);
    }
}

// ---------------------------------------------------------------------------
extern "C" void kernel_launch(void* const* d_in, const int* in_sizes, int n_in,
                              void* d_out, int out_size) {
    (void)in_sizes; (void)n_in; (void)out_size;
    const float* x = (const float*)d_in[0];  // (128, 9, 256)
    const float* W = (const float*)d_in[1];  // (3, 256, 256)
    const float* M = (const float*)d_in[2];  // (3, 1680, 9)
    float* out = (float*)d_out;              // (128, 1680, 256)

    gemm_z<<<dim3(18, 12, KSPLIT), 256>>>(x, W, M);
    perm_combine<<<dim3(NCHUNK, 2, BB), 256>>>(out);
}

// round 16
// speedup vs baseline: 1.1480x; 1.0434x over previous
#include <cuda_runtime.h>
#include <cstdint>

// Problem constants
#define BB    128
#define LL    9
#define KK    3
#define PP    1680
#define CIN   256
#define COUT  256
#define ZR    1152
#define ZC    768
#define KSPLIT 2

typedef unsigned long long u64;

// Scratch (device globals: allocation-free)
__device__ float  g_Z[KSPLIT * ZR * ZC];   // 6.8 MB, 2 K-partials
__device__ int    g_codes[PP];

__device__ __forceinline__ u64 pack2(float lo, float hi) {
    u64 r;
    asm("mov.b64 %0, {%1, %2};" : "=l"(r) : "f"(lo), "f"(hi));
    return r;
}
__device__ __forceinline__ void unpack2(float& lo, float& hi, u64 v) {
    asm("mov.b64 {%0, %1}, %2;" : "=f"(lo), "=f"(hi) : "l"(v));
}
__device__ __forceinline__ void ffma2(u64& d, u64 a, u64 b) {
    asm("fma.rn.f32x2 %0, %1, %2, %3;" : "=l"(d) : "l"(a), "l"(b), "l"(d));
}

// Swizzled transposed tile: logical [c][r]
// physical float offset = c*64 + 4*((r>>2) ^ ((c>>2)&15)) + (r&3)

// ---------------------------------------------------------------------------
// Kernel 1: GEMM partial. Z[ks][r,j] = sum_{c in ks*128..+128} X[r,c]*Wm[j,c]
// 64x64 tile, two 64-wide K chunks, XOR-swizzled transposed smem tiles,
// 4x4 reg tile via packed f32x2 FMAs, register prefetch. grid=(18,12,2).
// Blocks (bx<7, by==0, bz==0) also decode permutation codes from M.
// ---------------------------------------------------------------------------
__global__ void __launch_bounds__(256) gemm_z(const float* __restrict__ X,
                                              const float* __restrict__ Wm,
                                              const float* __restrict__ M) {
    __shared__ float sX[64 * 64];
    __shared__ float sW[64 * 64];

    const int t  = threadIdx.x;
    const int rb = blockIdx.x * 64;
    const int jb = blockIdx.y * 64;
    const int kb = blockIdx.z * 128;

    // fused code decode (7 blocks x 256 threads >= 1680)
    if (blockIdx.y == 0 && blockIdx.z == 0 && blockIdx.x < 7) {
        int p = blockIdx.x * 256 + t;
        if (p < PP) {
            const int PL = PP * LL;
            int c[3] = {0, 0, 0};
            const int w3[3] = {1, 3, 9};
#pragma unroll
            for (int l = 0; l < LL; l++) {
                float m1 = M[PL + p * LL + l];
                float m2 = M[2 * PL + p * LL + l];
                int a = (m1 > 0.5f) ? 1 : ((m2 > 0.5f) ? 2 : 0);
                c[l / 3] += a * w3[l % 3];
            }
            g_codes[p] = c[0] | (c[1] << 8) | (c[2] << 16);
        }
    }

    const int c4 = t & 15;
    const int rr = t >> 4;

    const int gx = t >> 4;
    const int gw = t & 15;
    const int row0 = gx * 4;
    const int col0 = gw * 4;

    u64 ap0[4] = {0, 0, 0, 0};
    u64 ap1[4] = {0, 0, 0, 0};

#pragma unroll
    for (int kk = 0; kk < 2; kk++) {
        const int kc = kb + kk * 64;
#pragma unroll
        for (int i = 0; i < 4; i++) {
            int r = rr + i * 16;
            int gs = (((r >> 2) ^ c4) << 2) + (r & 3);
            float4 v = *(const float4*)&X[(rb + r) * CIN + kc + c4 * 4];
            float* px = &sX[c4 * 256 + gs];
            px[0]   = v.x;
            px[64]  = v.y;
            px[128] = v.z;
            px[192] = v.w;
            float4 w = *(const float4*)&Wm[(jb + r) * CIN + kc + c4 * 4];
            float* pw = &sW[c4 * 256 + gs];
            pw[0]   = w.x;
            pw[64]  = w.y;
            pw[128] = w.z;
            pw[192] = w.w;
        }
        __syncthreads();

        ulonglong2 xp = *(const ulonglong2*)&sX[(gx ^ 0) << 2];
        float4     wv = *(const float4*)&sW[(gw ^ 0) << 2];
#pragma unroll
        for (int c = 0; c < 64; c++) {
            ulonglong2 xc = xp;
            float4 wc = wv;
            if (c < 63) {
                int key = ((c + 1) >> 2) & 15;
                xp = *(const ulonglong2*)&sX[(c + 1) * 64 + ((gx ^ key) << 2)];
                wv = *(const float4*)&sW[(c + 1) * 64 + ((gw ^ key) << 2)];
            }
            u64 w0 = pack2(wc.x, wc.x);
            u64 w1 = pack2(wc.y, wc.y);
            u64 w2 = pack2(wc.z, wc.z);
            u64 w3 = pack2(wc.w, wc.w);
            ffma2(ap0[0], xc.x, w0);
            ffma2(ap0[1], xc.x, w1);
            ffma2(ap0[2], xc.x, w2);
            ffma2(ap0[3], xc.x, w3);
            ffma2(ap1[0], xc.y, w0);
            ffma2(ap1[1], xc.y, w1);
            ffma2(ap1[2], xc.y, w2);
            ffma2(ap1[3], xc.y, w3);
        }
        __syncthreads();
    }

    float acc[4][4];
#pragma unroll
    for (int j = 0; j < 4; j++) {
        unpack2(acc[0][j], acc[1][j], ap0[j]);
        unpack2(acc[2][j], acc[3][j], ap1[j]);
    }
    float4* Z4 = (float4*)(g_Z + blockIdx.z * (ZR * ZC));
#pragma unroll
    for (int i = 0; i < 4; i++) {
        float4 v = make_float4(acc[i][0], acc[i][1], acc[i][2], acc[i][3]);
        Z4[(rb + row0 + i) * (ZC / 4) + (jb + col0) / 4] = v;
    }
}

// ---------------------------------------------------------------------------
// Kernel 2 (fused): combine, quarter-channel blocks for high occupancy.
// Stage this (b, quarter)'s summed Z slice (27 vrows x 16 f4, both
// K-partials) into smem, build the 81-entry table, stream 560 perms.
// grid = (3 p-chunks of 560, 4 channel quarters, 128 b) = 1536 blocks.
// smem ~= 20.7 + 6.75 + 2.2 KB ~= 30 KB -> 7 CTAs/SM.
// ---------------------------------------------------------------------------
#define PCHUNK 560
#define NCHUNK 3
#define Q4     16          // float4 per channel quarter

__global__ void __launch_bounds__(256) perm_combine(float* __restrict__ out) {
    __shared__ float4 sT4[81 * Q4];
    __shared__ float4 sZ[27 * Q4];
    __shared__ int sCodes[PCHUNK];

    const int t     = threadIdx.x;
    const int chunk = blockIdx.x;
    const int h     = blockIdx.y;   // channel quarter 0..3
    const int b     = blockIdx.z;
    const int pbase = chunk * PCHUNK;

    // ---- stage summed Z slice (both K-partials): vr = l*3 + k ----
    // NOTE: 27*Q4 = 432 > 256 threads -> strided loop (R15 bug was a plain if)
    const float4* Z0 = (const float4*)g_Z;
    const int pstride = (ZR * ZC) / 4;
    const int zb = b * LL * (ZC / 4) + h * Q4;
#pragma unroll 2
    for (int i = t; i < 27 * Q4; i += 256) {
        int vr = i >> 4;             // /Q4
        int o4 = i & (Q4 - 1);
        int l = vr / 3, k = vr - 3 * l;
        int idx = zb + l * (ZC / 4) + k * (COUT / 4) + o4;
        float4 a = Z0[idx];
        float4 bb = Z0[idx + pstride];
        float4 s;
        s.x = a.x + bb.x;
        s.y = a.y + bb.y;
        s.z = a.z + bb.z;
        s.w = a.w + bb.w;
        sZ[i] = s;
    }
#pragma unroll 2
    for (int i = t; i < PCHUNK; i += 256) sCodes[i] = g_codes[pbase + i];
    __syncthreads();

    // ---- build 81-entry table from smem ----
#pragma unroll 2
    for (int i = t; i < 81 * Q4; i += 256) {
        int cc = i >> 4;
        int o4 = i & (Q4 - 1);
        int g  = cc / 27;
        int c  = cc - g * 27;
        int d0 = c % 3, d1 = (c / 3) % 3, d2 = c / 9;
        float4 v0 = sZ[(9 * g + 0 + d0) * Q4 + o4];
        float4 v1 = sZ[(9 * g + 3 + d1) * Q4 + o4];
        float4 v2 = sZ[(9 * g + 6 + d2) * Q4 + o4];
        float4 s;
        s.x = v0.x + v1.x + v2.x;
        s.y = v0.y + v1.y + v2.y;
        s.z = v0.z + v1.z + v2.z;
        s.w = v0.w + v1.w + v2.w;
        sT4[i] = s;
    }
    __syncthreads();

    // ---- combine + stream out: 16 threads per p-row, 16 p per iter ----
    const int o4 = t & (Q4 - 1);
    const int pw = t >> 4;           // 0..15
    float4* out4 = (float4*)out;
    const int obase = (b * PP + pbase) * (COUT / 4) + h * Q4 + o4;

#pragma unroll 5
    for (int it = 0; it < PCHUNK / 16; it++) {
        int po   = it * 16 + pw;
        int code = sCodes[po];
        int c0 = code & 0xFF;
        int c1 = (code >> 8) & 0xFF;
        int c2 = (code >> 16) & 0xFF;
        float4 a  = sT4[c0 * Q4 + o4];
        float4 bb = sT4[(27 + c1) * Q4 + o4];
        float4 cv = sT4[(54 + c2) * Q4 + o4];
        float4 r;
        r.x = a.x + bb.x + cv.x;
        r.y = a.y + bb.y + cv.y;
        r.z = a.z + bb.z + cv.z;
        r.w = a.w + bb.w + cv.w;
        __stcs(&out4[obase + po * (COUT / 4)], r);
    }
}

// ---------------------------------------------------------------------------
extern "C" void kernel_launch(void* const* d_in, const int* in_sizes, int n_in,
                              void* d_out, int out_size) {
    (void)in_sizes; (void)n_in; (void)out_size;
    const float* x = (const float*)d_in[0];  // (128, 9, 256)
    const float* W = (const float*)d_in[1];  // (3, 256, 256)
    const float* M = (const float*)d_in[2];  // (3, 1680, 9)
    float* out = (float*)d_out;              // (128, 1680, 256)

    gemm_z<<<dim3(18, 12, KSPLIT), 256>>>(x, W, M);
    perm_combine<<<dim3(NCHUNK, 4, BB), 256>>>(out);
}